// round 2
// baseline (speedup 1.0000x reference)
#include <cuda_runtime.h>

// Problem constants: B=2, D=128^3 grid, C=3 channels, 7 squaring steps.
#define D 128
#define DMASK 127
#define D3 (D * D * D)          // 2097152
#define NVOX (2 * D3)           // 4194304 voxels total (B=2)
#define NTHREADS 256
#define NBLOCKS (NVOX / NTHREADS)

// Ping-pong scratch (48 MB). Device-global array: allocation-free per harness rules.
__device__ float g_scratch[NVOX * 3];

__global__ __launch_bounds__(NTHREADS) void intdvf_step_kernel(
    const float* __restrict__ in_ext,
    float* __restrict__ out_ext,
    int in_is_scratch,
    int out_is_scratch,
    float s)
{
    const float* __restrict__ in  = in_is_scratch  ? (const float*)g_scratch : in_ext;
    float* __restrict__ out       = out_is_scratch ? (float*)g_scratch       : out_ext;

    const int idx = blockIdx.x * NTHREADS + threadIdx.x;

    const int z = idx & DMASK;
    const int y = (idx >> 7) & DMASK;
    const int x = (idx >> 14) & DMASK;
    const int base = (idx >> 21) * (D3 * 3);   // batch offset in floats

    // Center value (the "+ ddf" term and the displacement source).
    const float* p = in + 3 * idx;
    const float vx = p[0];
    const float vy = p[1];
    const float vz = p[2];

    // Sample location = voxel coord + s * ddf (s=1/128 fuses the initial scaling exactly).
    const float lx = (float)x + s * vx;
    const float ly = (float)y + s * vy;
    const float lz = (float)z + s * vz;

    const float fx = floorf(lx), fy = floorf(ly), fz = floorf(lz);
    const float wx1 = lx - fx, wy1 = ly - fy, wz1 = lz - fz;
    const float wx0 = 1.0f - wx1, wy0 = 1.0f - wy1, wz0 = 1.0f - wz1;

    const int ix = (int)fx, iy = (int)fy, iz = (int)fz;

    // Clip corner indices to [0, 127]; weights stay unclipped (matches reference).
    const int ix0 = min(max(ix,     0), DMASK);
    const int ix1 = min(max(ix + 1, 0), DMASK);
    const int iy0 = min(max(iy,     0), DMASK);
    const int iy1 = min(max(iy + 1, 0), DMASK);
    const int iz0 = min(max(iz,     0), DMASK);
    const int iz1 = min(max(iz + 1, 0), DMASK);

    // Precompute float offsets (in floats, AoS stride 3).
    const int X0 = base + ix0 * (D * D * 3);
    const int X1 = base + ix1 * (D * D * 3);
    const int Y0 = iy0 * (D * 3);
    const int Y1 = iy1 * (D * 3);
    const int Z0 = iz0 * 3;
    const int Z1 = iz1 * 3;

    const float w00 = wx0 * wy0;
    const float w01 = wx0 * wy1;
    const float w10 = wx1 * wy0;
    const float w11 = wx1 * wy1;

    float ax = 0.0f, ay = 0.0f, az = 0.0f;
    const float* c;
    float w;

    // Corner order (bx, by, bz) — accumulation order irrelevant at 1e-3 tol.
    w = w00 * wz0; c = in + (X0 + Y0 + Z0);
    ax = fmaf(w, __ldg(c + 0), ax); ay = fmaf(w, __ldg(c + 1), ay); az = fmaf(w, __ldg(c + 2), az);

    w = w00 * wz1; c = in + (X0 + Y0 + Z1);
    ax = fmaf(w, __ldg(c + 0), ax); ay = fmaf(w, __ldg(c + 1), ay); az = fmaf(w, __ldg(c + 2), az);

    w = w01 * wz0; c = in + (X0 + Y1 + Z0);
    ax = fmaf(w, __ldg(c + 0), ax); ay = fmaf(w, __ldg(c + 1), ay); az = fmaf(w, __ldg(c + 2), az);

    w = w01 * wz1; c = in + (X0 + Y1 + Z1);
    ax = fmaf(w, __ldg(c + 0), ax); ay = fmaf(w, __ldg(c + 1), ay); az = fmaf(w, __ldg(c + 2), az);

    w = w10 * wz0; c = in + (X1 + Y0 + Z0);
    ax = fmaf(w, __ldg(c + 0), ax); ay = fmaf(w, __ldg(c + 1), ay); az = fmaf(w, __ldg(c + 2), az);

    w = w10 * wz1; c = in + (X1 + Y0 + Z1);
    ax = fmaf(w, __ldg(c + 0), ax); ay = fmaf(w, __ldg(c + 1), ay); az = fmaf(w, __ldg(c + 2), az);

    w = w11 * wz0; c = in + (X1 + Y1 + Z0);
    ax = fmaf(w, __ldg(c + 0), ax); ay = fmaf(w, __ldg(c + 1), ay); az = fmaf(w, __ldg(c + 2), az);

    w = w11 * wz1; c = in + (X1 + Y1 + Z1);
    ax = fmaf(w, __ldg(c + 0), ax); ay = fmaf(w, __ldg(c + 1), ay); az = fmaf(w, __ldg(c + 2), az);

    // out = s*ddf_center + s*trilerp  (power-of-two s distributes exactly)
    float* o = out + 3 * idx;
    o[0] = s * (vx + ax);
    o[1] = s * (vy + ay);
    o[2] = s * (vz + az);
}

extern "C" void kernel_launch(void* const* d_in, const int* in_sizes, int n_in,
                              void* d_out, int out_size)
{
    const float* dvf = (const float*)d_in[0];
    float* out = (float*)d_out;

    const float s0 = 1.0f / 128.0f;  // 2^-NUM_STEPS, exact

    // 7 steps; parity arranged so the final write lands in d_out:
    // step1: dvf -> out (s=1/128)
    // step2: out -> scratch
    // step3: scratch -> out
    // step4: out -> scratch
    // step5: scratch -> out
    // step6: out -> scratch
    // step7: scratch -> out
    intdvf_step_kernel<<<NBLOCKS, NTHREADS>>>(dvf, out, 0, 0, s0);
    intdvf_step_kernel<<<NBLOCKS, NTHREADS>>>(out, nullptr, 0, 1, 1.0f);
    intdvf_step_kernel<<<NBLOCKS, NTHREADS>>>(nullptr, out, 1, 0, 1.0f);
    intdvf_step_kernel<<<NBLOCKS, NTHREADS>>>(out, nullptr, 0, 1, 1.0f);
    intdvf_step_kernel<<<NBLOCKS, NTHREADS>>>(nullptr, out, 1, 0, 1.0f);
    intdvf_step_kernel<<<NBLOCKS, NTHREADS>>>(out, nullptr, 0, 1, 1.0f);
    intdvf_step_kernel<<<NBLOCKS, NTHREADS>>>(nullptr, out, 1, 0, 1.0f);
}

// round 3
// speedup vs baseline: 1.4379x; 1.4379x over previous
#include <cuda_runtime.h>

// Problem: B=2, 128^3 grid, C=3, 7 scaling-and-squaring steps.
#define D 128
#define DMASK 127
#define D3 (D * D * D)          // 2097152
#define NVOX (2 * D3)           // 4194304 voxels (B=2)
#define NTHREADS 256
#define NBLOCKS (NVOX / NTHREADS)

// Two SoA ping-pong buffers, 48 MB each. Layout: [comp][b*D3 + x*D*D + y*D + z].
__device__ float gA[3 * NVOX];
__device__ float gB[3 * NVOX];

// ---------------------------------------------------------------------------
// Transpose + scale: AoS dvf (float3 per voxel) -> SoA planes in gA, * 2^-7.
// Vectorized float4 reads (fully coalesced); scattered plane writes.
// ---------------------------------------------------------------------------
__global__ __launch_bounds__(NTHREADS) void transpose_scale_kernel(
    const float4* __restrict__ in4)
{
    const int i = blockIdx.x * NTHREADS + threadIdx.x;   // i < 3*NVOX/4
    const float s = 1.0f / 128.0f;                       // 2^-7, exact
    float4 v = in4[i];
    float vals[4] = {v.x, v.y, v.z, v.w};
    const int f = 4 * i;
    #pragma unroll
    for (int j = 0; j < 4; j++) {
        const int ff  = f + j;
        const int vox = ff / 3;
        const int c   = ff - 3 * vox;
        gA[c * NVOX + vox] = s * vals[j];
    }
}

// ---------------------------------------------------------------------------
// One squaring step, SoA -> SoA (or SoA -> AoS d_out on the last step).
// SRC: 1 = gA, 2 = gB.   DST: 0 = external AoS, 1 = gA, 2 = gB.
// ---------------------------------------------------------------------------
template <int SRC, int DST>
__global__ __launch_bounds__(NTHREADS) void step_soa_kernel(
    float* __restrict__ ext_out)
{
    const float* __restrict__ sx = (SRC == 1) ? gA : gB;
    const float* __restrict__ sy = sx + NVOX;
    const float* __restrict__ sz = sx + 2 * NVOX;

    const int idx = blockIdx.x * NTHREADS + threadIdx.x;

    const int z = idx & DMASK;
    const int y = (idx >> 7) & DMASK;
    const int x = (idx >> 14) & DMASK;
    const int bbase = (idx >> 21) * D3;

    // Center displacement (coalesced).
    const float vx = sx[idx];
    const float vy = sy[idx];
    const float vz = sz[idx];

    const float lx = (float)x + vx;
    const float ly = (float)y + vy;
    const float lz = (float)z + vz;

    const float fx = floorf(lx), fy = floorf(ly), fz = floorf(lz);
    const float wx1 = lx - fx, wy1 = ly - fy, wz1 = lz - fz;
    const float wx0 = 1.0f - wx1, wy0 = 1.0f - wy1, wz0 = 1.0f - wz1;

    const int ix = (int)fx, iy = (int)fy, iz = (int)fz;

    // Clip corner indices; weights stay unclipped (matches reference).
    const int ix0 = min(max(ix,     0), DMASK);
    const int ix1 = min(max(ix + 1, 0), DMASK);
    const int iy0 = min(max(iy,     0), DMASK);
    const int iy1 = min(max(iy + 1, 0), DMASK);
    const int iz0 = min(max(iz,     0), DMASK);
    const int iz1 = min(max(iz + 1, 0), DMASK);

    const int X0 = bbase + ix0 * (D * D);
    const int X1 = bbase + ix1 * (D * D);
    const int Y0 = iy0 * D;
    const int Y1 = iy1 * D;

    const float w00 = wx0 * wy0;
    const float w01 = wx0 * wy1;
    const float w10 = wx1 * wy0;
    const float w11 = wx1 * wy1;

    float ax = 0.0f, ay = 0.0f, az = 0.0f;

    #define CORNER(W, LIN)                                                    \
        do {                                                                  \
            const float w_ = (W);                                             \
            const int   l_ = (LIN);                                           \
            ax = fmaf(w_, __ldg(sx + l_), ax);                                \
            ay = fmaf(w_, __ldg(sy + l_), ay);                                \
            az = fmaf(w_, __ldg(sz + l_), az);                                \
        } while (0)

    CORNER(w00 * wz0, X0 + Y0 + iz0);
    CORNER(w00 * wz1, X0 + Y0 + iz1);
    CORNER(w01 * wz0, X0 + Y1 + iz0);
    CORNER(w01 * wz1, X0 + Y1 + iz1);
    CORNER(w10 * wz0, X1 + Y0 + iz0);
    CORNER(w10 * wz1, X1 + Y0 + iz1);
    CORNER(w11 * wz0, X1 + Y1 + iz0);
    CORNER(w11 * wz1, X1 + Y1 + iz1);
    #undef CORNER

    const float ox = vx + ax;
    const float oy = vy + ay;
    const float oz = vz + az;

    if (DST == 0) {
        // Final step: AoS float3 into d_out.
        float* o = ext_out + 3 * idx;
        o[0] = ox; o[1] = oy; o[2] = oz;
    } else {
        float* dx = (DST == 1) ? gA : gB;
        dx[idx]            = ox;
        dx[NVOX + idx]     = oy;
        dx[2 * NVOX + idx] = oz;
    }
}

extern "C" void kernel_launch(void* const* d_in, const int* in_sizes, int n_in,
                              void* d_out, int out_size)
{
    const float4* dvf4 = (const float4*)d_in[0];
    float* out = (float*)d_out;

    // AoS dvf -> scaled SoA in gA (ddf0 = dvf * 2^-7, exact).
    transpose_scale_kernel<<<(3 * NVOX / 4) / NTHREADS, NTHREADS>>>(dvf4);

    // 7 squaring steps, ping-pong; final step writes AoS into d_out.
    step_soa_kernel<1, 2><<<NBLOCKS, NTHREADS>>>(nullptr);  // 1: A -> B
    step_soa_kernel<2, 1><<<NBLOCKS, NTHREADS>>>(nullptr);  // 2: B -> A
    step_soa_kernel<1, 2><<<NBLOCKS, NTHREADS>>>(nullptr);  // 3: A -> B
    step_soa_kernel<2, 1><<<NBLOCKS, NTHREADS>>>(nullptr);  // 4: B -> A
    step_soa_kernel<1, 2><<<NBLOCKS, NTHREADS>>>(nullptr);  // 5: A -> B
    step_soa_kernel<2, 1><<<NBLOCKS, NTHREADS>>>(nullptr);  // 6: B -> A
    step_soa_kernel<1, 0><<<NBLOCKS, NTHREADS>>>(out);      // 7: A -> d_out
}